// round 2
// baseline (speedup 1.0000x reference)
#include <cuda_runtime.h>

// Problem constants
#define B_ 1024
#define N_ 64
#define F_ 64
#define E_ 16
#define M_ 128
#define O_ 128

// ---------------------------------------------------------------------------
// Scratch (device globals -- no allocation allowed)
// ---------------------------------------------------------------------------
__device__ float g_et2[B_ * N_ * F_];   // per-(b,v) folded edge term (16 MB)
__device__ float g_Wnb[F_ * F_];        // W_n @ W_u_bot   [64,64]
__device__ float g_Weu[E_ * F_];        // W_e @ W_u_bot   [16,64]
__device__ float g_cu [F_];             // b_m @ W_u_bot + b_u

// ---------------------------------------------------------------------------
// Kernel 0: fold weights.
// blocks 0..63  : row f of Wnb
// blocks 64..79 : row e of Weu
// block  80     : cu
// ---------------------------------------------------------------------------
__global__ void k_fold(const float* __restrict__ W_n, const float* __restrict__ W_e,
                       const float* __restrict__ b_m, const float* __restrict__ W_u,
                       const float* __restrict__ b_u)
{
    int bx = blockIdx.x, g = threadIdx.x;   // 64 threads
    if (bx < 64) {
        float acc = 0.f;
        #pragma unroll 8
        for (int m = 0; m < 128; m++)
            acc += W_n[bx * 128 + m] * W_u[(64 + m) * 64 + g];
        g_Wnb[bx * 64 + g] = acc;
    } else if (bx < 80) {
        int e = bx - 64;
        float acc = 0.f;
        #pragma unroll 8
        for (int m = 0; m < 128; m++)
            acc += W_e[e * 128 + m] * W_u[(64 + m) * 64 + g];
        g_Weu[e * 64 + g] = acc;
    } else {
        float acc = b_u[g];
        #pragma unroll 8
        for (int m = 0; m < 128; m++)
            acc += b_m[m] * W_u[(64 + m) * 64 + g];
        g_cu[g] = acc;
    }
}

// ---------------------------------------------------------------------------
// Kernel 1: et2[b,v,:] = cu + (sum_u adj[b,v,u] * edges[b,v,u,:]) @ Weu
// One warp per (b,v). Edge loads are skipped when adj==0 (halves DRAM traffic).
// ---------------------------------------------------------------------------
__global__ void __launch_bounds__(256)
k_edge(const int* __restrict__ adj, const float* __restrict__ edges)
{
    __shared__ float s_Weu[E_ * F_];
    __shared__ float s_cu[F_];
    int tid = threadIdx.x;
    for (int i = tid; i < E_ * F_; i += 256) s_Weu[i] = g_Weu[i];
    if (tid < F_) s_cu[tid] = g_cu[tid];
    __syncthreads();

    int lane = tid & 31;
    int bv = blockIdx.x * 8 + (tid >> 5);          // b*64 + v, 0..65535
    const int* arow = adj + bv * 64;
    const float* erow = edges + (long)bv * (64 * 16);

    float acc[16];
    #pragma unroll
    for (int e = 0; e < 16; e++) acc[e] = 0.f;

    #pragma unroll
    for (int s = 0; s < 2; s++) {
        int u = lane + s * 32;
        if (arow[u] != 0) {
            const float4* e4 = (const float4*)(erow + u * 16);
            float4 x0 = e4[0], x1 = e4[1], x2 = e4[2], x3 = e4[3];
            acc[0] += x0.x;  acc[1] += x0.y;  acc[2]  += x0.z;  acc[3]  += x0.w;
            acc[4] += x1.x;  acc[5] += x1.y;  acc[6]  += x1.z;  acc[7]  += x1.w;
            acc[8] += x2.x;  acc[9] += x2.y;  acc[10] += x2.z;  acc[11] += x2.w;
            acc[12]+= x3.x;  acc[13]+= x3.y;  acc[14] += x3.z;  acc[15] += x3.w;
        }
    }
    // butterfly reduce: afterwards every lane holds the full agg_e[0..15]
    #pragma unroll
    for (int off = 16; off > 0; off >>= 1) {
        #pragma unroll
        for (int e = 0; e < 16; e++)
            acc[e] += __shfl_xor_sync(0xffffffffu, acc[e], off);
    }

    float o0 = s_cu[lane], o1 = s_cu[lane + 32];
    #pragma unroll
    for (int e = 0; e < 16; e++) {
        o0 += acc[e] * s_Weu[e * 64 + lane];
        o1 += acc[e] * s_Weu[e * 64 + lane + 32];
    }
    g_et2[bv * 64 + lane]      = o0;
    g_et2[bv * 64 + lane + 32] = o1;
}

// ---------------------------------------------------------------------------
// Kernel 2: the 4 message passes + readout. One CTA per batch, all state in
// shared memory.
//
// smem layout (floats):
//   s_h    [0,    4160)  stride 65 (bank-conflict pad)
//   s_mask [4160, 4224)
//   s_red  [4224, 5248)
//   R = 5248, size 20544:
//     passes : s_adj R+0 (stride65, 4160), s_et R+4160 (4096),
//              s_T R+8256 (4096), s_Wnb R+12352 (4096), s_Wut R+16448 (4096)
//     readout: s_wr R+0 (16384 = W_r), s_nd R+16384 (4096 = nodes)
// total = 25792 floats = 103168 bytes -> 2 CTAs/SM
// ---------------------------------------------------------------------------
#define SMEM_BYTES (25792 * 4)

__global__ void __launch_bounds__(256, 2)
k_mpnn(const int* __restrict__ adj, const float* __restrict__ nodes,
       const float* __restrict__ W_u, const float* __restrict__ W_r,
       const float* __restrict__ b_r, float* __restrict__ out)
{
    extern __shared__ float sm[];
    float* s_h    = sm;
    float* s_mask = sm + 4160;
    float* s_red  = sm + 4224;
    float* R      = sm + 5248;
    float* s_adj  = R;
    float* s_et   = R + 4160;
    float* s_T    = R + 8256;
    float* s_Wnb  = R + 12352;
    float* s_Wut  = R + 16448;

    int tid = threadIdx.x;
    int b   = blockIdx.x;

    // ---- init loads ----
    const float* nb = nodes + b * 4096;
    const int*   ab = adj   + b * 4096;
    for (int i = tid; i < 4096; i += 256) {
        int v = i >> 6, f = i & 63;
        s_h  [v * 65 + f] = nb[i];
        s_adj[v * 65 + f] = (float)ab[i];
    }
    {
        const float4* src = (const float4*)(g_et2 + b * 4096);
        float4* dst = (float4*)s_et;
        for (int i = tid; i < 1024; i += 256) dst[i] = src[i];
        const float4* wnb = (const float4*)g_Wnb;
        float4* dW = (float4*)s_Wnb;
        for (int i = tid; i < 1024; i += 256) dW[i] = wnb[i];
        const float4* wu = (const float4*)W_u;    // rows 0..63 of W_u = W_u_top
        float4* dU = (float4*)s_Wut;
        for (int i = tid; i < 1024; i += 256) dU[i] = wu[i];
    }
    __syncthreads();
    if (tid < 64) {
        float s = 0.f;
        #pragma unroll 8
        for (int u = 0; u < 64; u++) s += s_adj[tid * 65 + u];
        s_mask[tid] = (s > 0.f) ? 1.f : 0.f;
    }
    __syncthreads();

    const int tx = tid & 15, ty = tid >> 4;
    const int g0 = tx * 4,  v0 = ty * 4;

    // ---- message passes ----
    for (int pass = 0; pass < 4; pass++) {
        // Phase A: G = h @ Wut (regs), T = h @ Wnb (smem)
        float G[4][4], T[4][4];
        #pragma unroll
        for (int i = 0; i < 4; i++)
            #pragma unroll
            for (int j = 0; j < 4; j++) { G[i][j] = 0.f; T[i][j] = 0.f; }

        #pragma unroll 4
        for (int f = 0; f < 64; f++) {
            float4 wn = *(const float4*)&s_Wnb[f * 64 + g0];
            float4 wu = *(const float4*)&s_Wut[f * 64 + g0];
            #pragma unroll
            for (int i = 0; i < 4; i++) {
                float hv = s_h[(v0 + i) * 65 + f];
                G[i][0] += hv * wu.x; G[i][1] += hv * wu.y;
                G[i][2] += hv * wu.z; G[i][3] += hv * wu.w;
                T[i][0] += hv * wn.x; T[i][1] += hv * wn.y;
                T[i][2] += hv * wn.z; T[i][3] += hv * wn.w;
            }
        }
        #pragma unroll
        for (int i = 0; i < 4; i++)
            *(float4*)&s_T[(v0 + i) * 64 + g0] =
                make_float4(T[i][0], T[i][1], T[i][2], T[i][3]);
        __syncthreads();

        // Phase B: S = adj @ T, then h_new = relu(G + S + et2), masked update
        float S[4][4];
        #pragma unroll
        for (int i = 0; i < 4; i++)
            #pragma unroll
            for (int j = 0; j < 4; j++) S[i][j] = 0.f;

        #pragma unroll 4
        for (int u = 0; u < 64; u++) {
            float4 t = *(const float4*)&s_T[u * 64 + g0];
            #pragma unroll
            for (int i = 0; i < 4; i++) {
                float a = s_adj[(v0 + i) * 65 + u];
                S[i][0] += a * t.x; S[i][1] += a * t.y;
                S[i][2] += a * t.z; S[i][3] += a * t.w;
            }
        }
        #pragma unroll
        for (int i = 0; i < 4; i++) {
            float m = s_mask[v0 + i];
            #pragma unroll
            for (int j = 0; j < 4; j++) {
                float pre = G[i][j] + S[i][j] + s_et[(v0 + i) * 64 + g0 + j];
                float nv  = fmaxf(pre, 0.f);
                float ov  = s_h[(v0 + i) * 65 + g0 + j];
                s_h[(v0 + i) * 65 + g0 + j] = (m != 0.f) ? nv : ov;
            }
        }
        __syncthreads();
    }

    // ---- readout: r = relu([h|nodes] @ W_r + b_r); out = sum_v mask*r ----
    float* s_wr = R;            // 128x128 W_r overlay
    float* s_nd = R + 16384;    // original nodes overlay
    for (int i = tid; i < 4096; i += 256) s_nd[i] = nb[i];
    {
        const float4* src = (const float4*)W_r;
        float4* dst = (float4*)s_wr;
        for (int i = tid; i < 4096; i += 256) dst[i] = src[i];
    }
    __syncthreads();

    const int rx = tid & 31, ry = tid >> 5;
    const int o0 = rx * 4;
    float4 br = *(const float4*)(b_r + o0);
    float oa0 = 0.f, oa1 = 0.f, oa2 = 0.f, oa3 = 0.f;
    for (int vv = 0; vv < 8; vv++) {
        int v = ry * 8 + vv;
        if (s_mask[v] != 0.f) {
            float r0 = br.x, r1 = br.y, r2 = br.z, r3 = br.w;
            #pragma unroll 4
            for (int k = 0; k < 64; k++) {
                float hv = s_h[v * 65 + k];
                float4 w = *(const float4*)&s_wr[k * 128 + o0];
                r0 += hv * w.x; r1 += hv * w.y; r2 += hv * w.z; r3 += hv * w.w;
            }
            #pragma unroll 4
            for (int k = 0; k < 64; k++) {
                float nv = s_nd[v * 64 + k];
                float4 w = *(const float4*)&s_wr[(64 + k) * 128 + o0];
                r0 += nv * w.x; r1 += nv * w.y; r2 += nv * w.z; r3 += nv * w.w;
            }
            oa0 += fmaxf(r0, 0.f); oa1 += fmaxf(r1, 0.f);
            oa2 += fmaxf(r2, 0.f); oa3 += fmaxf(r3, 0.f);
        }
    }
    *(float4*)&s_red[ry * 128 + o0] = make_float4(oa0, oa1, oa2, oa3);
    __syncthreads();
    if (tid < 128) {
        float s = 0.f;
        #pragma unroll
        for (int t = 0; t < 8; t++) s += s_red[t * 128 + tid];
        out[b * 128 + tid] = s;
    }
}

// ---------------------------------------------------------------------------
// Launch
// ---------------------------------------------------------------------------
extern "C" void kernel_launch(void* const* d_in, const int* in_sizes, int n_in,
                              void* d_out, int out_size)
{
    const int*   adj   = (const int*)  d_in[0];
    const float* nodes = (const float*)d_in[1];
    const float* edges = (const float*)d_in[2];
    const float* W_n   = (const float*)d_in[3];
    const float* W_e   = (const float*)d_in[4];
    const float* b_m   = (const float*)d_in[5];
    const float* W_u   = (const float*)d_in[6];
    const float* b_u   = (const float*)d_in[7];
    const float* W_r   = (const float*)d_in[8];
    const float* b_r   = (const float*)d_in[9];
    float* out = (float*)d_out;

    cudaFuncSetAttribute(k_mpnn, cudaFuncAttributeMaxDynamicSharedMemorySize,
                         SMEM_BYTES);

    k_fold<<<81, 64>>>(W_n, W_e, b_m, W_u, b_u);
    k_edge<<<8192, 256>>>(adj, edges);
    k_mpnn<<<1024, 256, SMEM_BYTES>>>(adj, nodes, W_u, W_r, b_r, out);
}

// round 3
// speedup vs baseline: 1.2002x; 1.2002x over previous
#include <cuda_runtime.h>

typedef unsigned long long u64;

// ---------------------------------------------------------------------------
// Scratch (device globals -- no allocation allowed)
// ---------------------------------------------------------------------------
__device__ float g_et2[1024 * 64 * 64];    // folded edge term (16 MB)
__device__ float g_nr [1024 * 64 * 128];   // nodes @ W_r_bot + b_r (32 MB)
__device__ float g_Wnb[64 * 64];           // W_n @ W_u_bot
__device__ float g_Weu[16 * 64];           // W_e @ W_u_bot
__device__ float g_cu [64];                // b_m @ W_u_bot + b_u
__device__ unsigned g_ctr;                 // persistent-CTA work counter

// ---------------------------------------------------------------------------
// Packed f32x2 helpers (Blackwell FFMA2 -- only reachable via PTX)
// ---------------------------------------------------------------------------
__device__ __forceinline__ u64 pk2(float lo, float hi) {
    u64 r; asm("mov.b64 %0, {%1, %2};" : "=l"(r) : "f"(lo), "f"(hi)); return r;
}
__device__ __forceinline__ void fma2(u64 &d, u64 a, u64 b) {
    asm("fma.rn.f32x2 %0, %1, %2, %0;" : "+l"(d) : "l"(a), "l"(b));
}
__device__ __forceinline__ void add2(u64 &d, u64 a) {
    asm("add.rn.f32x2 %0, %0, %1;" : "+l"(d) : "l"(a));
}
__device__ __forceinline__ void up2(u64 v, float &lo, float &hi) {
    asm("mov.b64 {%0, %1}, %2;" : "=f"(lo), "=f"(hi) : "l"(v));
}

// ---------------------------------------------------------------------------
// Kernel 0: fold weights (smem-staged, 10 blocks). Also resets work counter.
// ---------------------------------------------------------------------------
__global__ void __launch_bounds__(256)
k_fold(const float* __restrict__ W_n, const float* __restrict__ W_e,
       const float* __restrict__ b_m, const float* __restrict__ W_u,
       const float* __restrict__ b_u)
{
    __shared__ float s_Wu[128 * 64];   // W_u bottom rows 64..191
    __shared__ float s_A[16 * 128];
    int tid = threadIdx.x, bx = blockIdx.x;
    for (int i = tid; i < 8192; i += 256) s_Wu[i] = W_u[4096 + i];

    if (bx < 8) {                       // Wnb rows bx*8 .. bx*8+7
        for (int i = tid; i < 1024; i += 256) s_A[i] = W_n[bx * 1024 + i];
        __syncthreads();
        int g = tid & 63, r = tid >> 6;
        for (int rr = r; rr < 8; rr += 4) {
            float acc = 0.f;
            #pragma unroll 8
            for (int m = 0; m < 128; m++)
                acc += s_A[rr * 128 + m] * s_Wu[m * 64 + g];
            g_Wnb[(bx * 8 + rr) * 64 + g] = acc;
        }
    } else if (bx == 8) {               // Weu (16 rows)
        for (int i = tid; i < 2048; i += 256) s_A[i] = W_e[i];
        __syncthreads();
        int g = tid & 63, r = tid >> 6;
        for (int rr = r; rr < 16; rr += 4) {
            float acc = 0.f;
            #pragma unroll 8
            for (int m = 0; m < 128; m++)
                acc += s_A[rr * 128 + m] * s_Wu[m * 64 + g];
            g_Weu[rr * 64 + g] = acc;
        }
    } else {                            // cu + counter reset
        if (tid == 0) g_ctr = 0u;
        for (int i = tid; i < 128; i += 256) s_A[i] = b_m[i];
        __syncthreads();
        if (tid < 64) {
            float acc = b_u[tid];
            #pragma unroll 8
            for (int m = 0; m < 128; m++)
                acc += s_A[m] * s_Wu[m * 64 + tid];
            g_cu[tid] = acc;
        }
    }
}

// ---------------------------------------------------------------------------
// Kernel 1: per (b,v):
//   et2 = cu + (sum_u adj*edges) @ Weu          (memory-bound edge stream)
//   nr  = nodes @ W_r_bottom + b_r              (absorbed into spare FMA)
// One warp handles 4 bv values (amortizes the 32KB W_r smem stage).
// ---------------------------------------------------------------------------
__global__ void __launch_bounds__(256)
k_edge(const int* __restrict__ adj, const float* __restrict__ edges,
       const float* __restrict__ nodes, const float* __restrict__ W_r,
       const float* __restrict__ b_r)
{
    __shared__ float s_Weu[16 * 64];
    __shared__ float s_cu[64];
    __shared__ float s_Wr[64 * 128];     // W_r rows 64..127
    __shared__ float s_nrow[8][64];
    int tid = threadIdx.x;
    for (int i = tid; i < 1024; i += 256) s_Weu[i] = g_Weu[i];
    if (tid < 64) s_cu[tid] = g_cu[tid];
    for (int i = tid; i < 8192; i += 256) s_Wr[i] = W_r[8192 + i];
    __syncthreads();

    int w = tid >> 5, lane = tid & 31;
    for (int t = 0; t < 4; t++) {
        int bv = blockIdx.x * 32 + t * 8 + w;
        const int*   arow = adj   + bv * 64;
        const float* erow = edges + (long)bv * 1024;

        float acc[16];
        #pragma unroll
        for (int e = 0; e < 16; e++) acc[e] = 0.f;
        #pragma unroll
        for (int s = 0; s < 2; s++) {
            int u = lane + s * 32;
            if (arow[u] != 0) {
                const float4* e4 = (const float4*)(erow + u * 16);
                float4 x0 = e4[0], x1 = e4[1], x2 = e4[2], x3 = e4[3];
                acc[0] += x0.x;  acc[1] += x0.y;  acc[2]  += x0.z;  acc[3]  += x0.w;
                acc[4] += x1.x;  acc[5] += x1.y;  acc[6]  += x1.z;  acc[7]  += x1.w;
                acc[8] += x2.x;  acc[9] += x2.y;  acc[10] += x2.z;  acc[11] += x2.w;
                acc[12]+= x3.x;  acc[13]+= x3.y;  acc[14] += x3.z;  acc[15] += x3.w;
            }
        }
        #pragma unroll
        for (int off = 16; off > 0; off >>= 1) {
            #pragma unroll
            for (int e = 0; e < 16; e++)
                acc[e] += __shfl_xor_sync(0xffffffffu, acc[e], off);
        }
        float o0 = s_cu[lane], o1 = s_cu[lane + 32];
        #pragma unroll
        for (int e = 0; e < 16; e++) {
            o0 += acc[e] * s_Weu[e * 64 + lane];
            o1 += acc[e] * s_Weu[e * 64 + lane + 32];
        }
        g_et2[bv * 64 + lane]      = o0;
        g_et2[bv * 64 + lane + 32] = o1;

        // nr = nodes_row @ Wr_bot + b_r
        s_nrow[w][lane]      = nodes[bv * 64 + lane];
        s_nrow[w][lane + 32] = nodes[bv * 64 + lane + 32];
        __syncwarp();
        float4 r = *(const float4*)&b_r[lane * 4];
        #pragma unroll 8
        for (int k = 0; k < 64; k++) {
            float nk = s_nrow[w][k];
            float4 wr = *(const float4*)&s_Wr[k * 128 + lane * 4];
            r.x += nk * wr.x; r.y += nk * wr.y;
            r.z += nk * wr.z; r.w += nk * wr.w;
        }
        *(float4*)&g_nr[(long)bv * 128 + lane * 4] = r;
        __syncwarp();
    }
}

// ---------------------------------------------------------------------------
// Kernel 2: persistent CTAs; per batch: 4 passes (f32x2) + readout.
// smem (floats): s_hd[8192] dup-h | s_W[8192] | s_T[4096] | s_aT[4352] | s_mask[64]
// total 24896 floats = 99584 B -> 2 CTAs/SM
// ---------------------------------------------------------------------------
#define SMEM_BYTES (24896 * 4)

__global__ void __launch_bounds__(256, 2)
k_mpnn(const int* __restrict__ adj, const float* __restrict__ nodes,
       const float* __restrict__ W_u, const float* __restrict__ W_r,
       float* __restrict__ out)
{
    extern __shared__ float sm[];
    float* s_hd   = sm;            // [v*128 + 2f] duplicated h
    float* s_W    = sm + 8192;     // passes: [f][0:64]=Wu_top | [64:128]=Wnb ; readout: Wr_top
    float* s_T    = sm + 16384;    // [v][64]
    float* s_aT   = sm + 20480;    // adjT [u*68 + v]
    float* s_mask = sm + 24832;
    float* s_red  = s_T;           // readout overlay
    __shared__ unsigned s_b;

    int tid = threadIdx.x;
    const int tx = tid & 15, ty = tid >> 4;
    const int g0 = tx * 4,  v0 = ty * 4;
    const int rx = tid & 31, ry = tid >> 5;
    const int o0 = rx * 4;

    while (true) {
        if (tid == 0) s_b = atomicAdd(&g_ctr, 1u);
        __syncthreads();
        unsigned b = s_b;
        if (b >= 1024u) break;

        // ---- per-batch init ----
        const float* nb = nodes + b * 4096;
        const int*   ab = adj   + b * 4096;
        for (int i = tid; i < 4096; i += 256) {
            int v = i >> 6, u = i & 63;
            float hv = nb[i];
            s_hd[v * 128 + 2 * u]     = hv;
            s_hd[v * 128 + 2 * u + 1] = hv;
            s_aT[u * 68 + v] = (float)ab[i];
        }
        for (int i = tid; i < 4096; i += 256) {
            int f = i >> 6, g = i & 63;
            s_W[f * 128 + g]      = W_u[f * 64 + g];
            s_W[f * 128 + 64 + g] = g_Wnb[f * 64 + g];
        }
        ulonglong2 etp[4];
        #pragma unroll
        for (int i = 0; i < 4; i++)
            etp[i] = *(const ulonglong2*)&g_et2[(long)b * 4096 + (v0 + i) * 64 + g0];
        __syncthreads();
        if (tid < 64) {
            float s = 0.f;
            #pragma unroll 8
            for (int u = 0; u < 64; u++) s += s_aT[u * 68 + tid];
            s_mask[tid] = (s > 0.f) ? 1.f : 0.f;
        }
        __syncthreads();
        float mk[4];
        #pragma unroll
        for (int i = 0; i < 4; i++) mk[i] = s_mask[v0 + i];

        // ---- 4 message passes ----
        for (int pass = 0; pass < 4; pass++) {
            // Phase A: G = et2 + h@Wu_top (regs), T = h@Wnb (smem)
            u64 G[4][2], T[4][2];
            #pragma unroll
            for (int i = 0; i < 4; i++) {
                G[i][0] = etp[i].x; G[i][1] = etp[i].y;
                T[i][0] = 0ull;     T[i][1] = 0ull;
            }
            #pragma unroll 8
            for (int f = 0; f < 64; f++) {
                ulonglong2 wg = *(const ulonglong2*)&s_W[f * 128 + g0];
                ulonglong2 wt = *(const ulonglong2*)&s_W[f * 128 + 64 + g0];
                #pragma unroll
                for (int i = 0; i < 4; i++) {
                    u64 hp = *(const u64*)&s_hd[(v0 + i) * 128 + 2 * f];
                    fma2(G[i][0], hp, wg.x); fma2(G[i][1], hp, wg.y);
                    fma2(T[i][0], hp, wt.x); fma2(T[i][1], hp, wt.y);
                }
            }
            #pragma unroll
            for (int i = 0; i < 4; i++) {
                ulonglong2 tv; tv.x = T[i][0]; tv.y = T[i][1];
                *(ulonglong2*)&s_T[(v0 + i) * 64 + g0] = tv;
            }
            __syncthreads();

            // Phase B: S = adj @ T
            u64 S[4][2];
            #pragma unroll
            for (int i = 0; i < 4; i++) { S[i][0] = 0ull; S[i][1] = 0ull; }
            #pragma unroll 8
            for (int u = 0; u < 64; u++) {
                ulonglong2 tp = *(const ulonglong2*)&s_T[u * 64 + g0];
                float4 av = *(const float4*)&s_aT[u * 68 + v0];
                u64 a0 = pk2(av.x, av.x), a1 = pk2(av.y, av.y);
                u64 a2 = pk2(av.z, av.z), a3 = pk2(av.w, av.w);
                fma2(S[0][0], a0, tp.x); fma2(S[0][1], a0, tp.y);
                fma2(S[1][0], a1, tp.x); fma2(S[1][1], a1, tp.y);
                fma2(S[2][0], a2, tp.x); fma2(S[2][1], a2, tp.y);
                fma2(S[3][0], a3, tp.x); fma2(S[3][1], a3, tp.y);
            }
            // epilogue: h = relu(G + S) where mask, else unchanged
            #pragma unroll
            for (int i = 0; i < 4; i++) {
                if (mk[i] != 0.f) {
                    add2(G[i][0], S[i][0]); add2(G[i][1], S[i][1]);
                    float x0, x1, x2, x3;
                    up2(G[i][0], x0, x1); up2(G[i][1], x2, x3);
                    x0 = fmaxf(x0, 0.f); x1 = fmaxf(x1, 0.f);
                    x2 = fmaxf(x2, 0.f); x3 = fmaxf(x3, 0.f);
                    int base = (v0 + i) * 128 + 2 * g0;
                    s_hd[base]     = x0; s_hd[base + 1] = x0;
                    s_hd[base + 2] = x1; s_hd[base + 3] = x1;
                    s_hd[base + 4] = x2; s_hd[base + 5] = x2;
                    s_hd[base + 6] = x3; s_hd[base + 7] = x3;
                }
            }
            __syncthreads();
        }

        // ---- readout: out[o] = sum_v mask * relu(h@Wr_top + nr) ----
        for (int i = tid; i < 8192; i += 256) s_W[i] = W_r[i];  // Wr top rows
        ulonglong2 nrp[8];
        #pragma unroll
        for (int vv = 0; vv < 8; vv++)
            nrp[vv] = *(const ulonglong2*)&g_nr[((long)b * 64 + ry * 8 + vv) * 128 + o0];
        __syncthreads();

        u64 acc[8][2];
        #pragma unroll
        for (int vv = 0; vv < 8; vv++) { acc[vv][0] = 0ull; acc[vv][1] = 0ull; }
        #pragma unroll 4
        for (int k = 0; k < 64; k++) {
            ulonglong2 w = *(const ulonglong2*)&s_W[k * 128 + o0];
            #pragma unroll
            for (int vv = 0; vv < 8; vv++) {
                u64 hp = *(const u64*)&s_hd[(ry * 8 + vv) * 128 + 2 * k];
                fma2(acc[vv][0], hp, w.x); fma2(acc[vv][1], hp, w.y);
            }
        }
        float oa0 = 0.f, oa1 = 0.f, oa2 = 0.f, oa3 = 0.f;
        #pragma unroll
        for (int vv = 0; vv < 8; vv++) {
            if (s_mask[ry * 8 + vv] != 0.f) {
                add2(acc[vv][0], nrp[vv].x); add2(acc[vv][1], nrp[vv].y);
                float x0, x1, x2, x3;
                up2(acc[vv][0], x0, x1); up2(acc[vv][1], x2, x3);
                oa0 += fmaxf(x0, 0.f); oa1 += fmaxf(x1, 0.f);
                oa2 += fmaxf(x2, 0.f); oa3 += fmaxf(x3, 0.f);
            }
        }
        *(float4*)&s_red[ry * 128 + o0] = make_float4(oa0, oa1, oa2, oa3);
        __syncthreads();
        if (tid < 128) {
            float s = 0.f;
            #pragma unroll
            for (int t = 0; t < 8; t++) s += s_red[t * 128 + tid];
            out[b * 128 + tid] = s;
        }
        __syncthreads();
    }
}

// ---------------------------------------------------------------------------
// Launch
// ---------------------------------------------------------------------------
extern "C" void kernel_launch(void* const* d_in, const int* in_sizes, int n_in,
                              void* d_out, int out_size)
{
    const int*   adj   = (const int*)  d_in[0];
    const float* nodes = (const float*)d_in[1];
    const float* edges = (const float*)d_in[2];
    const float* W_n   = (const float*)d_in[3];
    const float* W_e   = (const float*)d_in[4];
    const float* b_m   = (const float*)d_in[5];
    const float* W_u   = (const float*)d_in[6];
    const float* b_u   = (const float*)d_in[7];
    const float* W_r   = (const float*)d_in[8];
    const float* b_r   = (const float*)d_in[9];
    float* out = (float*)d_out;

    cudaFuncSetAttribute(k_mpnn, cudaFuncAttributeMaxDynamicSharedMemorySize,
                         SMEM_BYTES);

    k_fold<<<10, 256>>>(W_n, W_e, b_m, W_u, b_u);
    k_edge<<<2048, 256>>>(adj, edges, nodes, W_r, b_r);
    k_mpnn<<<296, 256, SMEM_BYTES>>>(adj, nodes, W_u, W_r, out);
}

// round 4
// speedup vs baseline: 1.2233x; 1.0192x over previous
#include <cuda_runtime.h>

typedef unsigned long long u64;

// ---------------------------------------------------------------------------
// Scratch (device globals -- no allocation allowed)
// ---------------------------------------------------------------------------
__device__ float g_agg[1024 * 64 * 16];    // raw edge aggregation (4 MB)
__device__ float g_nr [1024 * 64 * 128];   // nodes @ W_r_bot + b_r (32 MB)
__device__ float g_Wnb[64 * 64];           // W_n @ W_u_bot
__device__ float g_Weu[16 * 64];           // W_e @ W_u_bot
__device__ float g_cu [64];                // b_m @ W_u_bot + b_u
__device__ unsigned g_ctr;                 // persistent-CTA work counter

// ---------------------------------------------------------------------------
// Packed f32x2 helpers (Blackwell FFMA2 -- only reachable via PTX)
// ---------------------------------------------------------------------------
__device__ __forceinline__ u64 pk2(float lo, float hi) {
    u64 r; asm("mov.b64 %0, {%1, %2};" : "=l"(r) : "f"(lo), "f"(hi)); return r;
}
__device__ __forceinline__ void fma2(u64 &d, u64 a, u64 b) {
    asm("fma.rn.f32x2 %0, %1, %2, %0;" : "+l"(d) : "l"(a), "l"(b));
}
__device__ __forceinline__ void add2(u64 &d, u64 a) {
    asm("add.rn.f32x2 %0, %0, %1;" : "+l"(d) : "l"(a));
}
__device__ __forceinline__ void up2(u64 v, float &lo, float &hi) {
    asm("mov.b64 {%0, %1}, %2;" : "=f"(lo), "=f"(hi) : "l"(v));
}

// ---------------------------------------------------------------------------
// Kernel 1 (k_pre): role-split grid.
//  blocks 0..2047   : per (b,v) raw edge aggregation -> g_agg, and
//                     nr = nodes @ W_r_bottom + b_r -> g_nr   (f32x2)
//  blocks 2048..2055: Wnb fold rows
//  block  2056      : Weu fold + cu + counter reset
// ---------------------------------------------------------------------------
__global__ void __launch_bounds__(256)
k_pre(const int* __restrict__ adj, const float* __restrict__ edges,
      const float* __restrict__ nodes,
      const float* __restrict__ W_n, const float* __restrict__ W_e,
      const float* __restrict__ b_m, const float* __restrict__ W_u,
      const float* __restrict__ b_u,
      const float* __restrict__ W_r, const float* __restrict__ b_r)
{
    __shared__ float buf[8192 + 2048];   // 40 KB static
    int bx = blockIdx.x, tid = threadIdx.x;

    if (bx < 2048) {
        float* s_Wr   = buf;                       // W_r rows 64..127 (8192)
        float* s_nrow = buf + 8192;                // 8 warps x 64
        for (int i = tid; i < 8192; i += 256) s_Wr[i] = W_r[8192 + i];
        __syncthreads();

        int w = tid >> 5, lane = tid & 31;
        for (int t = 0; t < 4; t++) {
            int bv = bx * 32 + t * 8 + w;
            const int*   arow = adj   + bv * 64;
            const float* erow = edges + (long)bv * 1024;

            float acc[16];
            #pragma unroll
            for (int e = 0; e < 16; e++) acc[e] = 0.f;
            #pragma unroll
            for (int s = 0; s < 2; s++) {
                int u = lane + s * 32;
                if (arow[u] != 0) {
                    const float4* e4 = (const float4*)(erow + u * 16);
                    float4 x0 = e4[0], x1 = e4[1], x2 = e4[2], x3 = e4[3];
                    acc[0] += x0.x;  acc[1] += x0.y;  acc[2]  += x0.z;  acc[3]  += x0.w;
                    acc[4] += x1.x;  acc[5] += x1.y;  acc[6]  += x1.z;  acc[7]  += x1.w;
                    acc[8] += x2.x;  acc[9] += x2.y;  acc[10] += x2.z;  acc[11] += x2.w;
                    acc[12]+= x3.x;  acc[13]+= x3.y;  acc[14] += x3.z;  acc[15] += x3.w;
                }
            }
            #pragma unroll
            for (int off = 16; off > 0; off >>= 1) {
                #pragma unroll
                for (int e = 0; e < 16; e++)
                    acc[e] += __shfl_xor_sync(0xffffffffu, acc[e], off);
            }
            if (lane == 0) {
                float4* dst = (float4*)(g_agg + bv * 16);
                dst[0] = make_float4(acc[0],  acc[1],  acc[2],  acc[3]);
                dst[1] = make_float4(acc[4],  acc[5],  acc[6],  acc[7]);
                dst[2] = make_float4(acc[8],  acc[9],  acc[10], acc[11]);
                dst[3] = make_float4(acc[12], acc[13], acc[14], acc[15]);
            }

            // nr = nodes_row @ Wr_bot + b_r  (f32x2)
            s_nrow[w * 64 + lane]      = nodes[bv * 64 + lane];
            s_nrow[w * 64 + lane + 32] = nodes[bv * 64 + lane + 32];
            __syncwarp();
            ulonglong2 r = *(const ulonglong2*)&b_r[lane * 4];
            #pragma unroll 4
            for (int k = 0; k < 64; k++) {
                float nk = s_nrow[w * 64 + k];
                u64 nkp = pk2(nk, nk);
                ulonglong2 w2 = *(const ulonglong2*)&s_Wr[k * 128 + lane * 4];
                fma2(r.x, nkp, w2.x); fma2(r.y, nkp, w2.y);
            }
            *(ulonglong2*)&g_nr[(long)bv * 128 + lane * 4] = r;
            __syncwarp();
        }
    } else {
        float* s_Wu = buf;                 // W_u bottom rows (8192)
        float* s_A  = buf + 8192;          // operand rows (<=2048)
        for (int i = tid; i < 8192; i += 256) s_Wu[i] = W_u[4096 + i];

        if (bx < 2056) {                   // Wnb rows (bx-2048)*8 ..+8
            int r0 = (bx - 2048) * 8;
            for (int i = tid; i < 1024; i += 256) s_A[i] = W_n[r0 * 128 + i];
            __syncthreads();
            int g = tid & 63, r = tid >> 6;
            for (int rr = r; rr < 8; rr += 4) {
                float acc = 0.f;
                #pragma unroll 8
                for (int m = 0; m < 128; m++)
                    acc += s_A[rr * 128 + m] * s_Wu[m * 64 + g];
                g_Wnb[(r0 + rr) * 64 + g] = acc;
            }
        } else {                           // Weu + cu + ctr
            if (tid == 0) g_ctr = 0u;
            for (int i = tid; i < 2048; i += 256) s_A[i] = W_e[i];
            __syncthreads();
            int g = tid & 63, r = tid >> 6;
            for (int rr = r; rr < 16; rr += 4) {
                float acc = 0.f;
                #pragma unroll 8
                for (int m = 0; m < 128; m++)
                    acc += s_A[rr * 128 + m] * s_Wu[m * 64 + g];
                g_Weu[rr * 64 + g] = acc;
            }
            if (tid < 64) {
                float acc = b_u[tid];
                #pragma unroll 8
                for (int m = 0; m < 128; m++)
                    acc += b_m[m] * s_Wu[m * 64 + tid];
                g_cu[tid] = acc;
            }
        }
    }
}

// ---------------------------------------------------------------------------
// Kernel 2 (k_mpnn): persistent CTAs; 4 passes (f32x2) + readout per batch.
// smem (floats):
//   s_hd [0,8320)       dup-h, row stride 130 (conflict-free half-warp pairs)
//   s_W  [8320,16512)   passes: Wu_top|Wnb interleaved; readout: Wr_top
//   s_T  [16512,20608)  Phase-A T tile; init: agg/Weu/cu staging; readout: red
//   s_aT [20608,24960)  adjacency transposed, stride 68
//   s_mask [24960,25024)
// total 25024 floats = 100096 B -> 2 CTAs/SM
// ---------------------------------------------------------------------------
#define SMEM_BYTES (25024 * 4)

__global__ void __launch_bounds__(256, 2)
k_mpnn(const int* __restrict__ adj, const float* __restrict__ nodes,
       const float* __restrict__ W_u, const float* __restrict__ W_r,
       float* __restrict__ out)
{
    extern __shared__ float sm[];
    float* s_hd   = sm;
    float* s_W    = sm + 8320;
    float* s_T    = sm + 16512;
    float* s_aT   = sm + 20608;
    float* s_mask = sm + 24960;
    float* s_red  = s_T;
    __shared__ unsigned s_b;

    int tid = threadIdx.x;
    const int tx = tid & 15, ty = tid >> 4;
    const int g0 = tx * 4,  v0 = ty * 4;
    const int rx = tid & 31, ry = tid >> 5;
    const int o0 = rx * 4;

    while (true) {
        if (tid == 0) s_b = atomicAdd(&g_ctr, 1u);
        __syncthreads();
        unsigned b = s_b;
        if (b >= 1024u) break;

        // ---- per-batch init ----
        const float* nb = nodes + b * 4096;
        const int*   ab = adj   + b * 4096;
        for (int i = tid; i < 4096; i += 256) {
            int v = i >> 6, u = i & 63;
            float hv = nb[i];
            s_hd[v * 130 + 2 * u]     = hv;
            s_hd[v * 130 + 2 * u + 1] = hv;
            s_aT[u * 68 + v] = (float)ab[i];
        }
        for (int i = tid; i < 4096; i += 256) {
            int f = i >> 6, g = i & 63;
            s_W[f * 128 + g]      = W_u[f * 64 + g];
            s_W[f * 128 + 64 + g] = g_Wnb[f * 64 + g];
        }
        // stage agg / Weu / cu into s_T (free until Phase A writes it)
        for (int i = tid; i < 1024; i += 256) {
            s_T[i]        = g_agg[(long)b * 1024 + i];
            s_T[1024 + i] = g_Weu[i];
        }
        if (tid < 64) s_T[2048 + tid] = g_cu[tid];
        __syncthreads();

        if (tid < 64) {
            float s = 0.f;
            #pragma unroll 8
            for (int u = 0; u < 64; u++) s += s_aT[u * 68 + tid];
            s_mask[tid] = (s > 0.f) ? 1.f : 0.f;
        }
        // et2 tile for this thread: et2[v][g] = cu[g] + agg[v][:] @ Weu[:, g]
        ulonglong2 etp[4];
        {
            float4 cu4 = *(const float4*)&s_T[2048 + g0];
            #pragma unroll
            for (int i = 0; i < 4; i++) {
                float e0 = cu4.x, e1 = cu4.y, e2 = cu4.z, e3 = cu4.w;
                #pragma unroll
                for (int e = 0; e < 16; e++) {
                    float a = s_T[(v0 + i) * 16 + e];
                    float4 w4 = *(const float4*)&s_T[1024 + e * 64 + g0];
                    e0 += a * w4.x; e1 += a * w4.y; e2 += a * w4.z; e3 += a * w4.w;
                }
                etp[i].x = pk2(e0, e1); etp[i].y = pk2(e2, e3);
            }
        }
        __syncthreads();
        float mk[4];
        #pragma unroll
        for (int i = 0; i < 4; i++) mk[i] = s_mask[v0 + i];

        // ---- 4 message passes ----
        for (int pass = 0; pass < 4; pass++) {
            // Phase A: G = et2 + h@Wu_top (regs), T = h@Wnb (smem)
            u64 G[4][2], T[4][2];
            #pragma unroll
            for (int i = 0; i < 4; i++) {
                G[i][0] = etp[i].x; G[i][1] = etp[i].y;
                T[i][0] = 0ull;     T[i][1] = 0ull;
            }
            #pragma unroll 4
            for (int f = 0; f < 64; f++) {
                ulonglong2 wg = *(const ulonglong2*)&s_W[f * 128 + g0];
                ulonglong2 wt = *(const ulonglong2*)&s_W[f * 128 + 64 + g0];
                #pragma unroll
                for (int i = 0; i < 4; i++) {
                    u64 hp = *(const u64*)&s_hd[(v0 + i) * 130 + 2 * f];
                    fma2(G[i][0], hp, wg.x); fma2(G[i][1], hp, wg.y);
                    fma2(T[i][0], hp, wt.x); fma2(T[i][1], hp, wt.y);
                }
            }
            #pragma unroll
            for (int i = 0; i < 4; i++) {
                ulonglong2 tv; tv.x = T[i][0]; tv.y = T[i][1];
                *(ulonglong2*)&s_T[(v0 + i) * 64 + g0] = tv;
            }
            __syncthreads();

            // Phase B: S = adj @ T
            u64 S[4][2];
            #pragma unroll
            for (int i = 0; i < 4; i++) { S[i][0] = 0ull; S[i][1] = 0ull; }
            #pragma unroll 4
            for (int u = 0; u < 64; u++) {
                ulonglong2 tp = *(const ulonglong2*)&s_T[u * 64 + g0];
                float4 av = *(const float4*)&s_aT[u * 68 + v0];
                u64 a0 = pk2(av.x, av.x), a1 = pk2(av.y, av.y);
                u64 a2 = pk2(av.z, av.z), a3 = pk2(av.w, av.w);
                fma2(S[0][0], a0, tp.x); fma2(S[0][1], a0, tp.y);
                fma2(S[1][0], a1, tp.x); fma2(S[1][1], a1, tp.y);
                fma2(S[2][0], a2, tp.x); fma2(S[2][1], a2, tp.y);
                fma2(S[3][0], a3, tp.x); fma2(S[3][1], a3, tp.y);
            }
            // epilogue: h = relu(G + S) where mask, else unchanged
            #pragma unroll
            for (int i = 0; i < 4; i++) {
                if (mk[i] != 0.f) {
                    add2(G[i][0], S[i][0]); add2(G[i][1], S[i][1]);
                    float x0, x1, x2, x3;
                    up2(G[i][0], x0, x1); up2(G[i][1], x2, x3);
                    x0 = fmaxf(x0, 0.f); x1 = fmaxf(x1, 0.f);
                    x2 = fmaxf(x2, 0.f); x3 = fmaxf(x3, 0.f);
                    int base = (v0 + i) * 130 + 2 * g0;
                    s_hd[base]     = x0; s_hd[base + 1] = x0;
                    s_hd[base + 2] = x1; s_hd[base + 3] = x1;
                    s_hd[base + 4] = x2; s_hd[base + 5] = x2;
                    s_hd[base + 6] = x3; s_hd[base + 7] = x3;
                }
            }
            __syncthreads();
        }

        // ---- readout: out[o] = sum_v mask * relu(h@Wr_top + nr) ----
        for (int i = tid; i < 8192; i += 256) s_W[i] = W_r[i];  // Wr top rows
        ulonglong2 nrp[8];
        #pragma unroll
        for (int vv = 0; vv < 8; vv++)
            nrp[vv] = *(const ulonglong2*)&g_nr[((long)b * 64 + ry * 8 + vv) * 128 + o0];
        __syncthreads();

        u64 acc[8][2];
        #pragma unroll
        for (int vv = 0; vv < 8; vv++) { acc[vv][0] = 0ull; acc[vv][1] = 0ull; }
        #pragma unroll 2
        for (int k = 0; k < 64; k++) {
            ulonglong2 w = *(const ulonglong2*)&s_W[k * 128 + o0];
            #pragma unroll
            for (int vv = 0; vv < 8; vv++) {
                u64 hp = *(const u64*)&s_hd[(ry * 8 + vv) * 130 + 2 * k];
                fma2(acc[vv][0], hp, w.x); fma2(acc[vv][1], hp, w.y);
            }
        }
        float oa0 = 0.f, oa1 = 0.f, oa2 = 0.f, oa3 = 0.f;
        #pragma unroll
        for (int vv = 0; vv < 8; vv++) {
            if (s_mask[ry * 8 + vv] != 0.f) {
                add2(acc[vv][0], nrp[vv].x); add2(acc[vv][1], nrp[vv].y);
                float x0, x1, x2, x3;
                up2(acc[vv][0], x0, x1); up2(acc[vv][1], x2, x3);
                oa0 += fmaxf(x0, 0.f); oa1 += fmaxf(x1, 0.f);
                oa2 += fmaxf(x2, 0.f); oa3 += fmaxf(x3, 0.f);
            }
        }
        __syncthreads();   // passes' s_T use done; reuse as reduction buffer
        *(float4*)&s_red[ry * 128 + o0] = make_float4(oa0, oa1, oa2, oa3);
        __syncthreads();
        if (tid < 128) {
            float s = 0.f;
            #pragma unroll
            for (int t = 0; t < 8; t++) s += s_red[t * 128 + tid];
            out[b * 128 + tid] = s;
        }
        __syncthreads();
    }
}

// ---------------------------------------------------------------------------
// Launch
// ---------------------------------------------------------------------------
extern "C" void kernel_launch(void* const* d_in, const int* in_sizes, int n_in,
                              void* d_out, int out_size)
{
    const int*   adj   = (const int*)  d_in[0];
    const float* nodes = (const float*)d_in[1];
    const float* edges = (const float*)d_in[2];
    const float* W_n   = (const float*)d_in[3];
    const float* W_e   = (const float*)d_in[4];
    const float* b_m   = (const float*)d_in[5];
    const float* W_u   = (const float*)d_in[6];
    const float* b_u   = (const float*)d_in[7];
    const float* W_r   = (const float*)d_in[8];
    const float* b_r   = (const float*)d_in[9];
    float* out = (float*)d_out;

    cudaFuncSetAttribute(k_mpnn, cudaFuncAttributeMaxDynamicSharedMemorySize,
                         SMEM_BYTES);

    k_pre<<<2057, 256>>>(adj, edges, nodes, W_n, W_e, b_m, W_u, b_u, W_r, b_r);
    k_mpnn<<<296, 256, SMEM_BYTES>>>(adj, nodes, W_u, W_r, out);
}